// round 8
// baseline (speedup 1.0000x reference)
#include <cuda_runtime.h>
#include <cuda_bf16.h>
#include <math.h>

#define Bq     16
#define Nn     1024
#define Dd     128
#define VOCABq 32000
#define HOPSq  3
#define HEADSq 4
#define KMAX   128
#define ALPHAq 0.2f
#define ROWS   (Bq * Nn)   // 16384
#define KTOT   512
#define K2TOT  256          // packed bf16x2 words per row
#define NHOP   (HOPSq + 1)

// ---------------- device scratch ----------------
__device__ int      g_nbr_idx[ROWS * KMAX];
__device__ int      g_nbr_cnt[ROWS];
__device__ float    g_X4[NHOP * ROWS * Dd];
__device__ float    g_wa1[16 * Dd];
__device__ float    g_wa2[16 * Dd];
__device__ float    g_f1[NHOP * HEADSq * ROWS];
__device__ float    g_f2[NHOP * HEADSq * ROWS];
__device__ unsigned g_Yhi[ROWS * K2TOT];         // bf16x2 (adjacent k) hi
__device__ unsigned g_Ylo[ROWS * K2TOT];         // bf16x2 lo residual
__device__ unsigned g_Whi[NHOP * K2TOT * Dd];    // [hop][k2][n] packed bf16x2
__device__ unsigned g_Wlo[NHOP * K2TOT * Dd];
__device__ float    g_G[NHOP * ROWS * Dd];
__device__ float    g_u[Bq * Dd];
__device__ float    g_logits[ROWS];

// ---------------- bf16 helpers ----------------
__device__ __forceinline__ void split_bf16(float x, float& hi, float& lo) {
    __nv_bfloat16 h = __float2bfloat16_rn(x);
    hi = __bfloat162float(h);
    lo = x - hi;
}
__device__ __forceinline__ unsigned pack2(float e0, float e1) {
    __nv_bfloat162 p = __floats2bfloat162_rn(e0, e1);
    return *reinterpret_cast<unsigned*>(&p);
}
__device__ __forceinline__ void mma_bf16(float* c, const unsigned* a, const unsigned* b) {
    asm volatile(
        "mma.sync.aligned.m16n8k16.row.col.f32.bf16.bf16.f32 "
        "{%0,%1,%2,%3}, {%4,%5,%6,%7}, {%8,%9}, {%0,%1,%2,%3};"
        : "+f"(c[0]), "+f"(c[1]), "+f"(c[2]), "+f"(c[3])
        : "r"(a[0]), "r"(a[1]), "r"(a[2]), "r"(a[3]), "r"(b[0]), "r"(b[1]));
}

// ---------------- neighbor list (float4 + warp scan) ----------------
__global__ void k_build_nbr(const float* __restrict__ adj,
                            const int* __restrict__ kb_len,
                            const int* __restrict__ conv_len) {
    int warp = (blockIdx.x * blockDim.x + threadIdx.x) >> 5;
    int lane = threadIdx.x & 31;
    if (warp >= ROWS) return;
    int b = warp / Nn, n = warp % Nn;
    int ctx = kb_len[b] + conv_len[b];
    const float* arow = adj + (size_t)warp * Nn;
    int* idx = g_nbr_idx + (size_t)warp * KMAX;
    int cnt = 0;
    bool self_ok = (n >= ctx);
    for (int m0 = 0; m0 < Nn; m0 += 128) {
        int mb = m0 + lane * 4;
        float4 a = *(const float4*)(arow + mb);
        bool s0 = (a.x > 0.0f) || (self_ok && mb == n);
        bool s1 = (a.y > 0.0f) || (self_ok && mb + 1 == n);
        bool s2 = (a.z > 0.0f) || (self_ok && mb + 2 == n);
        bool s3 = (a.w > 0.0f) || (self_ok && mb + 3 == n);
        int loc = (int)s0 + (int)s1 + (int)s2 + (int)s3;
        int sc = loc;
#pragma unroll
        for (int o = 1; o < 32; o <<= 1) {
            int t = __shfl_up_sync(0xffffffffu, sc, o);
            if (lane >= o) sc += t;
        }
        int w = cnt + sc - loc;
        if (s0) { if (w < KMAX) idx[w] = mb;     w++; }
        if (s1) { if (w < KMAX) idx[w] = mb + 1; w++; }
        if (s2) { if (w < KMAX) idx[w] = mb + 2; w++; }
        if (s3) { if (w < KMAX) idx[w] = mb + 3; w++; }
        cnt += __shfl_sync(0xffffffffu, sc, 31);
    }
    if (lane == 0) g_nbr_cnt[warp] = cnt < KMAX ? cnt : KMAX;
}

// ---------------- wa = W @ a ----------------
__global__ void k_proj(const float* __restrict__ W_all, const float* __restrict__ a_all) {
    int hh = blockIdx.x;
    int d = threadIdx.x;
    const float* Wrow = W_all + ((size_t)hh * Dd + d) * Dd;
    const float* a = a_all + (size_t)hh * 2 * Dd;
    float s1 = 0.f, s2 = 0.f;
#pragma unroll 4
    for (int e = 0; e < Dd; e++) {
        float w = Wrow[e];
        s1 += w * a[e];
        s2 += w * a[Dd + e];
    }
    g_wa1[hh * Dd + d] = s1;
    g_wa2[hh * Dd + d] = s2;
}

// ---------------- pre-split W into packed bf16 hi/lo ([k2][n]) ----------------
__global__ void k_split_W(const float* __restrict__ W_all) {
    size_t i = (size_t)blockIdx.x * blockDim.x + threadIdx.x;
    if (i >= (size_t)NHOP * K2TOT * Dd) return;
    size_t hop = i / ((size_t)K2TOT * Dd);
    size_t r = i % ((size_t)K2TOT * Dd);
    size_t k2 = r / Dd, nn = r % Dd;
    const float* Wh = W_all + hop * KTOT * Dd;
    float w0 = Wh[(2 * k2) * Dd + nn];
    float w1 = Wh[(2 * k2 + 1) * Dd + nn];
    float h0, l0, h1, l1;
    split_bf16(w0, h0, l0);
    split_bf16(w1, h1, l1);
    g_Whi[i] = pack2(h0, h1);
    g_Wlo[i] = pack2(l0, l1);
}

// ---------------- embedding + LM add + fused f1/f2 (all hops) ----------------
__global__ void k_embed_f(const int* __restrict__ story,
                          const int* __restrict__ kb_len,
                          const int* __restrict__ conv_len,
                          const float* __restrict__ dh,
                          const float* __restrict__ emb) {
    int hop = blockIdx.y;
    __shared__ float swa1[HEADSq * Dd];
    __shared__ float swa2[HEADSq * Dd];
    for (int t = threadIdx.x; t < HEADSq * Dd; t += blockDim.x) {
        swa1[t] = g_wa1[hop * HEADSq * Dd + t];
        swa2[t] = g_wa2[hop * HEADSq * Dd + t];
    }
    __syncthreads();
    int warp = (blockIdx.x * blockDim.x + threadIdx.x) >> 5;
    int lane = threadIdx.x & 31;
    if (warp >= ROWS) return;
    int b = warp / Nn, n = warp % Nn;
    const int* st = story + (size_t)warp * 4;
    int i0 = st[0], i1 = st[1], i2 = st[2], i3 = st[3];
    const float* E = emb + (size_t)hop * VOCABq * Dd;
    int d = lane * 4;
    float4 v0 = *(const float4*)(E + (size_t)i0 * Dd + d);
    float4 v1 = *(const float4*)(E + (size_t)i1 * Dd + d);
    float4 v2 = *(const float4*)(E + (size_t)i2 * Dd + d);
    float4 v3 = *(const float4*)(E + (size_t)i3 * Dd + d);
    float4 s;
    s.x = v0.x + v1.x + v2.x + v3.x;
    s.y = v0.y + v1.y + v2.y + v3.y;
    s.z = v0.z + v1.z + v2.z + v3.z;
    s.w = v0.w + v1.w + v2.w + v3.w;
    int rel = n - (kb_len[b] - 1);
    if (rel >= 0 && rel < conv_len[b]) {
        float4 g = *(const float4*)(dh + ((size_t)b * Nn + rel) * Dd + d);
        s.x += g.x; s.y += g.y; s.z += g.z; s.w += g.w;
    }
    *(float4*)(g_X4 + ((size_t)hop * ROWS + warp) * Dd + d) = s;

    float p1[HEADSq], p2[HEADSq];
#pragma unroll
    for (int h = 0; h < HEADSq; h++) {
        const float* w1 = swa1 + h * Dd + d;
        const float* w2 = swa2 + h * Dd + d;
        p1[h] = s.x * w1[0] + s.y * w1[1] + s.z * w1[2] + s.w * w1[3];
        p2[h] = s.x * w2[0] + s.y * w2[1] + s.z * w2[2] + s.w * w2[3];
    }
#pragma unroll
    for (int o = 16; o; o >>= 1)
#pragma unroll
        for (int h = 0; h < HEADSq; h++) {
            p1[h] += __shfl_xor_sync(0xffffffffu, p1[h], o);
            p2[h] += __shfl_xor_sync(0xffffffffu, p2[h], o);
        }
    if (lane == 0)
#pragma unroll
        for (int h = 0; h < HEADSq; h++) {
            g_f1[((size_t)hop * HEADSq + h) * ROWS + warp] = p1[h];
            g_f2[((size_t)hop * HEADSq + h) * ROWS + warp] = p2[h];
        }
}

// ------ sparse GAT attention (per hop): aggregate X -> packed (Yhi, Ylo) ------
__global__ void k_attn_agg(int hop) {
    __shared__ float sw[8][HEADSq][KMAX];
    int wl = threadIdx.x >> 5;
    int warp = blockIdx.x * 8 + wl;
    int lane = threadIdx.x & 31;
    if (warp >= ROWS) return;
    int b = warp / Nn;
    int cnt = g_nbr_cnt[warp];
    const int* idx = g_nbr_idx + (size_t)warp * KMAX;
    int d = lane * 4;
    const float* X = g_X4 + (size_t)hop * ROWS * Dd;
    float4 acc[HEADSq];
#pragma unroll
    for (int h = 0; h < HEADSq; h++) acc[h] = make_float4(0.f, 0.f, 0.f, 0.f);

    if (cnt == 0) {
        float4 a = make_float4(0.f, 0.f, 0.f, 0.f);
        for (int m = 0; m < Nn; m++) {
            float4 v = *(const float4*)(X + ((size_t)b * Nn + m) * Dd + d);
            a.x += v.x; a.y += v.y; a.z += v.z; a.w += v.w;
        }
        float sc = 1.0f / (float)Nn;
        a.x *= sc; a.y *= sc; a.z *= sc; a.w *= sc;
#pragma unroll
        for (int h = 0; h < HEADSq; h++) acc[h] = a;
    } else {
        float f1h[HEADSq];
#pragma unroll
        for (int h = 0; h < HEADSq; h++)
            f1h[h] = g_f1[((size_t)hop * HEADSq + h) * ROWS + warp];
        float mx[HEADSq];
#pragma unroll
        for (int h = 0; h < HEADSq; h++) mx[h] = -3.4e38f;
        for (int j = lane; j < cnt; j += 32) {
            int m = idx[j];
#pragma unroll
            for (int h = 0; h < HEADSq; h++) {
                float v = f1h[h] + g_f2[((size_t)hop * HEADSq + h) * ROWS + b * Nn + m];
                v = (v >= 0.0f) ? v : ALPHAq * v;
                sw[wl][h][j] = v;
                mx[h] = fmaxf(mx[h], v);
            }
        }
#pragma unroll
        for (int o = 16; o; o >>= 1)
#pragma unroll
            for (int h = 0; h < HEADSq; h++)
                mx[h] = fmaxf(mx[h], __shfl_xor_sync(0xffffffffu, mx[h], o));
        __syncwarp();
        float sum[HEADSq] = {0.f, 0.f, 0.f, 0.f};
        for (int j = lane; j < cnt; j += 32) {
#pragma unroll
            for (int h = 0; h < HEADSq; h++) {
                float w = expf(sw[wl][h][j] - mx[h]);
                sw[wl][h][j] = w;
                sum[h] += w;
            }
        }
#pragma unroll
        for (int o = 16; o; o >>= 1)
#pragma unroll
            for (int h = 0; h < HEADSq; h++)
                sum[h] += __shfl_xor_sync(0xffffffffu, sum[h], o);
        float sc[HEADSq];
#pragma unroll
        for (int h = 0; h < HEADSq; h++) sc[h] = 1.0f / sum[h];
        __syncwarp();
        for (int j = 0; j < cnt; j++) {
            int m = idx[j];
            float4 xv = *(const float4*)(X + ((size_t)b * Nn + m) * Dd + d);
#pragma unroll
            for (int h = 0; h < HEADSq; h++) {
                float w = sw[wl][h][j] * sc[h];
                acc[h].x += w * xv.x; acc[h].y += w * xv.y;
                acc[h].z += w * xv.z; acc[h].w += w * xv.w;
            }
        }
    }
    size_t base = (size_t)warp * K2TOT;
#pragma unroll
    for (int h = 0; h < HEADSq; h++) {
        float hx, lx, hy, ly, hz, lz, hw, lw;
        split_bf16(acc[h].x, hx, lx);
        split_bf16(acc[h].y, hy, ly);
        split_bf16(acc[h].z, hz, lz);
        split_bf16(acc[h].w, hw, lw);
        uint2 whi = make_uint2(pack2(hx, hy), pack2(hz, hw));
        uint2 wlo = make_uint2(pack2(lx, ly), pack2(lz, lw));
        *(uint2*)(g_Yhi + base + h * 64 + lane * 2) = whi;
        *(uint2*)(g_Ylo + base + h * 64 + lane * 2) = wlo;
    }
}

// ------ G[hop] = 0.25 * Y (16384x512) @ W[hop] (512x128), 3x bf16 MMA ------
// 64-row tiles, 256 CTAs, 2 CTAs/SM
#define MTq 64
__global__ void __launch_bounds__(256, 2) k_gemm_G(int hop) {
    __shared__ unsigned Ah[2][MTq][9];   // [m][k2 words]
    __shared__ unsigned Al[2][MTq][9];
    __shared__ unsigned Bh[2][8][132];   // [k2][n]
    __shared__ unsigned Bl[2][8][132];
    int row0 = blockIdx.x * MTq;
    const unsigned* AH = g_Yhi + (size_t)row0 * K2TOT;
    const unsigned* AL = g_Ylo + (size_t)row0 * K2TOT;
    const unsigned* BH = g_Whi + (size_t)hop * K2TOT * Dd;
    const unsigned* BL = g_Wlo + (size_t)hop * K2TOT * Dd;
    int tid = threadIdx.x;
    int lane = tid & 31, wid = tid >> 5;
    int wm = wid & 3, wn = wid >> 2;          // warp tile 16m x 64n
    int gid = lane >> 2, tig = lane & 3;

    int am = tid >> 1;                         // 0..127 (only <64 used by A)
    int aw0 = (tid & 1) * 4;
    int bk2 = tid >> 5;                        // 0..7
    int bn0 = lane * 4;
    bool a_ld = (tid < 128);

    uint4 pah, pal, pbh, pbl;
    if (a_ld) {
        pah = *(const uint4*)(AH + (size_t)am * K2TOT + aw0);
        pal = *(const uint4*)(AL + (size_t)am * K2TOT + aw0);
    }
    pbh = *(const uint4*)(BH + (size_t)bk2 * Dd + bn0);
    pbl = *(const uint4*)(BL + (size_t)bk2 * Dd + bn0);
    if (a_ld) {
        Ah[0][am][aw0 + 0] = pah.x; Ah[0][am][aw0 + 1] = pah.y;
        Ah[0][am][aw0 + 2] = pah.z; Ah[0][am][aw0 + 3] = pah.w;
        Al[0][am][aw0 + 0] = pal.x; Al[0][am][aw0 + 1] = pal.y;
        Al[0][am][aw0 + 2] = pal.z; Al[0][am][aw0 + 3] = pal.w;
    }
    *(uint4*)&Bh[0][bk2][bn0] = pbh;
    *(uint4*)&Bl[0][bk2][bn0] = pbl;
    __syncthreads();

    float acc[8][4];
#pragma unroll
    for (int nt = 0; nt < 8; nt++)
#pragma unroll
        for (int q = 0; q < 4; q++) acc[nt][q] = 0.0f;

    int buf = 0;
    const int NSTEP = K2TOT / 8;               // 32 chunks (k=16 each)
    for (int kt = 0; kt < NSTEP; kt++) {
        if (kt < NSTEP - 1) {
            int k0 = (kt + 1) * 8;
            if (a_ld) {
                pah = *(const uint4*)(AH + (size_t)am * K2TOT + k0 + aw0);
                pal = *(const uint4*)(AL + (size_t)am * K2TOT + k0 + aw0);
            }
            pbh = *(const uint4*)(BH + (size_t)(k0 + bk2) * Dd + bn0);
            pbl = *(const uint4*)(BL + (size_t)(k0 + bk2) * Dd + bn0);
        }
        unsigned ah[4], al[4];
        {
            int m0 = wm * 16 + gid;
            ah[0] = Ah[buf][m0][tig];
            ah[1] = Ah[buf][m0 + 8][tig];
            ah[2] = Ah[buf][m0][tig + 4];
            ah[3] = Ah[buf][m0 + 8][tig + 4];
            al[0] = Al[buf][m0][tig];
            al[1] = Al[buf][m0 + 8][tig];
            al[2] = Al[buf][m0][tig + 4];
            al[3] = Al[buf][m0 + 8][tig + 4];
        }
#pragma unroll
        for (int nt = 0; nt < 8; nt++) {
            int n0 = wn * 64 + nt * 8 + gid;
            unsigned bh[2], bl[2];
            bh[0] = Bh[buf][tig][n0];
            bh[1] = Bh[buf][tig + 4][n0];
            bl[0] = Bl[buf][tig][n0];
            bl[1] = Bl[buf][tig + 4][n0];
            mma_bf16(acc[nt], ah, bh);
            mma_bf16(acc[nt], al, bh);
            mma_bf16(acc[nt], ah, bl);
        }
        if (kt < NSTEP - 1) {
            buf ^= 1;
            if (a_ld) {
                Ah[buf][am][aw0 + 0] = pah.x; Ah[buf][am][aw0 + 1] = pah.y;
                Ah[buf][am][aw0 + 2] = pah.z; Ah[buf][am][aw0 + 3] = pah.w;
                Al[buf][am][aw0 + 0] = pal.x; Al[buf][am][aw0 + 1] = pal.y;
                Al[buf][am][aw0 + 2] = pal.z; Al[buf][am][aw0 + 3] = pal.w;
            }
            *(uint4*)&Bh[buf][bk2][bn0] = pbh;
            *(uint4*)&Bl[buf][bk2][bn0] = pbl;
            __syncthreads();
        }
    }

    float* G = g_G + ((size_t)hop * ROWS + row0) * Dd;
#pragma unroll
    for (int nt = 0; nt < 8; nt++) {
        int r = wm * 16 + gid;
        int c = wn * 64 + nt * 8 + 2 * tig;
        float2 o0 = make_float2(acc[nt][0] * 0.25f, acc[nt][1] * 0.25f);
        float2 o1 = make_float2(acc[nt][2] * 0.25f, acc[nt][3] * 0.25f);
        *(float2*)(G + (size_t)r * Dd + c) = o0;
        *(float2*)(G + (size_t)(r + 8) * Dd + c) = o1;
    }
}

// ---------------- hop recurrence (fully fused, 1 block per batch) ----------------
__global__ void k_init_u(const float* __restrict__ hidden) {
    int i = blockIdx.x * blockDim.x + threadIdx.x;
    if (i < Bq * Dd) g_u[i] = hidden[i];
}

__global__ void __launch_bounds__(1024) k_hop(int hop) {
    int b = blockIdx.x;
    int tid = threadIdx.x, wid = tid >> 5, lane = tid & 31;
    __shared__ float lg[Nn];
    __shared__ float red[32];
    __shared__ float s_mx, s_inv;

    // phase 1: logits[n] = dot(G[hop][b,n,:], u[b,:])
    const float* Gh = g_G + (size_t)hop * ROWS * Dd + (size_t)b * Nn * Dd;
    float4 u4 = *(const float4*)(g_u + (size_t)b * Dd + lane * 4);
#pragma unroll 4
    for (int j = 0; j < 32; j++) {
        int n = wid * 32 + j;
        float4 g = *(const float4*)(Gh + (size_t)n * Dd + lane * 4);
        float s = g.x * u4.x + g.y * u4.y + g.z * u4.z + g.w * u4.w;
#pragma unroll
        for (int o = 16; o; o >>= 1) s += __shfl_xor_sync(0xffffffffu, s, o);
        if (lane == 0) lg[n] = s;
    }
    __syncthreads();
    g_logits[(size_t)b * Nn + tid] = lg[tid];

    // phase 2: softmax stats
    float v = lg[tid];
    float m = v;
#pragma unroll
    for (int o = 16; o; o >>= 1) m = fmaxf(m, __shfl_xor_sync(0xffffffffu, m, o));
    if (lane == 0) red[wid] = m;
    __syncthreads();
    if (wid == 0) {
        float t = red[lane];
#pragma unroll
        for (int o = 16; o; o >>= 1) t = fmaxf(t, __shfl_xor_sync(0xffffffffu, t, o));
        if (lane == 0) s_mx = t;
    }
    __syncthreads();
    float p = expf(v - s_mx);
    float sm = p;
#pragma unroll
    for (int o = 16; o; o >>= 1) sm += __shfl_xor_sync(0xffffffffu, sm, o);
    if (lane == 0) red[wid] = sm;
    __syncthreads();
    lg[tid] = p;
    if (wid == 0) {
        float t = red[lane];
#pragma unroll
        for (int o = 16; o; o >>= 1) t += __shfl_xor_sync(0xffffffffu, t, o);
        if (lane == 0) s_inv = 1.0f / t;
    }
    __syncthreads();

    // phase 3: du[d] = sum_n p[n] * G[hop+1][b,n,d]
    int d = tid & 127, grp = tid >> 7;          // 8 groups
    const float* Gn = g_G + (size_t)(hop + 1) * ROWS * Dd + (size_t)b * Nn * Dd;
    float du = 0.0f;
    for (int n = grp; n < Nn; n += 8) du += lg[n] * Gn[(size_t)n * Dd + d];
    __syncthreads();
    lg[tid] = du;
    __syncthreads();
    if (grp == 0) {
        float t = 0.0f;
#pragma unroll
        for (int c = 0; c < 8; c++) t += lg[c * 128 + d];
        g_u[(size_t)b * Dd + d] += t * s_inv;
    }
}

// ---------------- outputs ----------------
__global__ void k_final(float* __restrict__ out) {
    int i = blockIdx.x * blockDim.x + threadIdx.x;
    if (i < ROWS) {
        float l = g_logits[i];
        out[i] = 1.0f / (1.0f + expf(-l));
        out[ROWS + Bq * Dd + i] = l;
    }
    if (i < Bq * Dd) out[ROWS + i] = g_u[i];
}

// ---------------- launch ----------------
extern "C" void kernel_launch(void* const* d_in, const int* in_sizes, int n_in,
                              void* d_out, int out_size) {
    const int*   story  = (const int*)d_in[0];
    const int*   kb     = (const int*)d_in[1];
    const int*   cv     = (const int*)d_in[2];
    const float* hidden = (const float*)d_in[3];
    const float* dh     = (const float*)d_in[4];
    const float* adj    = (const float*)d_in[5];
    const float* emb    = (const float*)d_in[6];
    const float* W      = (const float*)d_in[7];
    const float* a      = (const float*)d_in[8];
    float* out = (float*)d_out;

    k_build_nbr<<<2048, 256>>>(adj, kb, cv);
    k_init_u<<<8, 256>>>(hidden);
    k_proj<<<16, 128>>>(W, a);
    k_split_W<<<(NHOP * K2TOT * Dd + 255) / 256, 256>>>(W);
    k_embed_f<<<dim3(2048, NHOP), 256>>>(story, kb, cv, dh, emb);

    for (int k = 0; k < NHOP; k++) {
        k_attn_agg<<<2048, 256>>>(k);
        k_gemm_G<<<256, 256>>>(k);
    }

    for (int hop = 0; hop < HOPSq; hop++)
        k_hop<<<Bq, 1024>>>(hop);

    k_final<<<(ROWS + 255) / 256, 256>>>(out);
}

// round 9
// speedup vs baseline: 1.3991x; 1.3991x over previous
#include <cuda_runtime.h>
#include <cuda_bf16.h>
#include <math.h>

#define Bq     16
#define Nn     1024
#define Dd     128
#define VOCABq 32000
#define HOPSq  3
#define HEADSq 4
#define KMAX   128
#define ALPHAq 0.2f
#define ROWS   (Bq * Nn)   // 16384
#define KTOT   512
#define K2TOT  256          // packed bf16x2 words per row
#define NHOP   (HOPSq + 1)

// ---------------- device scratch ----------------
__device__ int      g_nbr_idx[ROWS * KMAX];
__device__ int      g_nbr_cnt[ROWS];
__device__ float    g_X4[NHOP * ROWS * Dd];
__device__ float    g_wa1[16 * Dd];
__device__ float    g_wa2[16 * Dd];
__device__ float    g_f1[NHOP * HEADSq * ROWS];
__device__ float    g_f2[NHOP * HEADSq * ROWS];
__device__ unsigned g_Yhi[ROWS * K2TOT];         // bf16x2 (adjacent k) hi
__device__ unsigned g_Ylo[ROWS * K2TOT];         // bf16x2 lo residual
__device__ unsigned g_Whi[NHOP * K2TOT * Dd];    // [hop][k2][n] packed bf16x2
__device__ unsigned g_Wlo[NHOP * K2TOT * Dd];
__device__ float    g_G[NHOP * ROWS * Dd];
__device__ float    g_u[Bq * Dd];
__device__ float    g_logits[ROWS];
__device__ float    g_stats[Bq * 2];
__device__ float    g_dupart[Bq * 32 * Dd];

// ---------------- bf16 helpers ----------------
__device__ __forceinline__ void split_bf16(float x, float& hi, float& lo) {
    __nv_bfloat16 h = __float2bfloat16_rn(x);
    hi = __bfloat162float(h);
    lo = x - hi;
}
__device__ __forceinline__ unsigned pack2(float e0, float e1) {
    __nv_bfloat162 p = __floats2bfloat162_rn(e0, e1);
    return *reinterpret_cast<unsigned*>(&p);
}
__device__ __forceinline__ void mma_bf16(float* c, const unsigned* a, const unsigned* b) {
    asm volatile(
        "mma.sync.aligned.m16n8k16.row.col.f32.bf16.bf16.f32 "
        "{%0,%1,%2,%3}, {%4,%5,%6,%7}, {%8,%9}, {%0,%1,%2,%3};"
        : "+f"(c[0]), "+f"(c[1]), "+f"(c[2]), "+f"(c[3])
        : "r"(a[0]), "r"(a[1]), "r"(a[2]), "r"(a[3]), "r"(b[0]), "r"(b[1]));
}

// ---------------- neighbor list (float4 + warp scan) ----------------
__global__ void k_build_nbr(const float* __restrict__ adj,
                            const int* __restrict__ kb_len,
                            const int* __restrict__ conv_len) {
    int warp = (blockIdx.x * blockDim.x + threadIdx.x) >> 5;
    int lane = threadIdx.x & 31;
    if (warp >= ROWS) return;
    int b = warp / Nn, n = warp % Nn;
    int ctx = kb_len[b] + conv_len[b];
    const float* arow = adj + (size_t)warp * Nn;
    int* idx = g_nbr_idx + (size_t)warp * KMAX;
    int cnt = 0;
    bool self_ok = (n >= ctx);
    for (int m0 = 0; m0 < Nn; m0 += 128) {
        int mb = m0 + lane * 4;
        float4 a = *(const float4*)(arow + mb);
        bool s0 = (a.x > 0.0f) || (self_ok && mb == n);
        bool s1 = (a.y > 0.0f) || (self_ok && mb + 1 == n);
        bool s2 = (a.z > 0.0f) || (self_ok && mb + 2 == n);
        bool s3 = (a.w > 0.0f) || (self_ok && mb + 3 == n);
        int loc = (int)s0 + (int)s1 + (int)s2 + (int)s3;
        int sc = loc;
#pragma unroll
        for (int o = 1; o < 32; o <<= 1) {
            int t = __shfl_up_sync(0xffffffffu, sc, o);
            if (lane >= o) sc += t;
        }
        int w = cnt + sc - loc;
        if (s0) { if (w < KMAX) idx[w] = mb;     w++; }
        if (s1) { if (w < KMAX) idx[w] = mb + 1; w++; }
        if (s2) { if (w < KMAX) idx[w] = mb + 2; w++; }
        if (s3) { if (w < KMAX) idx[w] = mb + 3; w++; }
        cnt += __shfl_sync(0xffffffffu, sc, 31);
    }
    if (lane == 0) g_nbr_cnt[warp] = cnt < KMAX ? cnt : KMAX;
}

// ---------------- wa = W @ a ----------------
__global__ void k_proj(const float* __restrict__ W_all, const float* __restrict__ a_all) {
    int hh = blockIdx.x;
    int d = threadIdx.x;
    const float* Wrow = W_all + ((size_t)hh * Dd + d) * Dd;
    const float* a = a_all + (size_t)hh * 2 * Dd;
    float s1 = 0.f, s2 = 0.f;
#pragma unroll 4
    for (int e = 0; e < Dd; e++) {
        float w = Wrow[e];
        s1 += w * a[e];
        s2 += w * a[Dd + e];
    }
    g_wa1[hh * Dd + d] = s1;
    g_wa2[hh * Dd + d] = s2;
}

// ---------------- pre-split W into packed bf16 hi/lo ([k2][n]) ----------------
__global__ void k_split_W(const float* __restrict__ W_all) {
    size_t i = (size_t)blockIdx.x * blockDim.x + threadIdx.x;
    if (i >= (size_t)NHOP * K2TOT * Dd) return;
    size_t hop = i / ((size_t)K2TOT * Dd);
    size_t r = i % ((size_t)K2TOT * Dd);
    size_t k2 = r / Dd, nn = r % Dd;
    const float* Wh = W_all + hop * KTOT * Dd;
    float w0 = Wh[(2 * k2) * Dd + nn];
    float w1 = Wh[(2 * k2 + 1) * Dd + nn];
    float h0, l0, h1, l1;
    split_bf16(w0, h0, l0);
    split_bf16(w1, h1, l1);
    g_Whi[i] = pack2(h0, h1);
    g_Wlo[i] = pack2(l0, l1);
}

// ---------------- embedding + LM add + fused f1/f2 (all hops) ----------------
__global__ void k_embed_f(const int* __restrict__ story,
                          const int* __restrict__ kb_len,
                          const int* __restrict__ conv_len,
                          const float* __restrict__ dh,
                          const float* __restrict__ emb) {
    int hop = blockIdx.y;
    __shared__ float swa1[HEADSq * Dd];
    __shared__ float swa2[HEADSq * Dd];
    for (int t = threadIdx.x; t < HEADSq * Dd; t += blockDim.x) {
        swa1[t] = g_wa1[hop * HEADSq * Dd + t];
        swa2[t] = g_wa2[hop * HEADSq * Dd + t];
    }
    __syncthreads();
    int warp = (blockIdx.x * blockDim.x + threadIdx.x) >> 5;
    int lane = threadIdx.x & 31;
    if (warp >= ROWS) return;
    int b = warp / Nn, n = warp % Nn;
    const int* st = story + (size_t)warp * 4;
    int i0 = st[0], i1 = st[1], i2 = st[2], i3 = st[3];
    const float* E = emb + (size_t)hop * VOCABq * Dd;
    int d = lane * 4;
    float4 v0 = *(const float4*)(E + (size_t)i0 * Dd + d);
    float4 v1 = *(const float4*)(E + (size_t)i1 * Dd + d);
    float4 v2 = *(const float4*)(E + (size_t)i2 * Dd + d);
    float4 v3 = *(const float4*)(E + (size_t)i3 * Dd + d);
    float4 s;
    s.x = v0.x + v1.x + v2.x + v3.x;
    s.y = v0.y + v1.y + v2.y + v3.y;
    s.z = v0.z + v1.z + v2.z + v3.z;
    s.w = v0.w + v1.w + v2.w + v3.w;
    int rel = n - (kb_len[b] - 1);
    if (rel >= 0 && rel < conv_len[b]) {
        float4 g = *(const float4*)(dh + ((size_t)b * Nn + rel) * Dd + d);
        s.x += g.x; s.y += g.y; s.z += g.z; s.w += g.w;
    }
    *(float4*)(g_X4 + ((size_t)hop * ROWS + warp) * Dd + d) = s;

    float p1[HEADSq], p2[HEADSq];
#pragma unroll
    for (int h = 0; h < HEADSq; h++) {
        const float* w1 = swa1 + h * Dd + d;
        const float* w2 = swa2 + h * Dd + d;
        p1[h] = s.x * w1[0] + s.y * w1[1] + s.z * w1[2] + s.w * w1[3];
        p2[h] = s.x * w2[0] + s.y * w2[1] + s.z * w2[2] + s.w * w2[3];
    }
#pragma unroll
    for (int o = 16; o; o >>= 1)
#pragma unroll
        for (int h = 0; h < HEADSq; h++) {
            p1[h] += __shfl_xor_sync(0xffffffffu, p1[h], o);
            p2[h] += __shfl_xor_sync(0xffffffffu, p2[h], o);
        }
    if (lane == 0)
#pragma unroll
        for (int h = 0; h < HEADSq; h++) {
            g_f1[((size_t)hop * HEADSq + h) * ROWS + warp] = p1[h];
            g_f2[((size_t)hop * HEADSq + h) * ROWS + warp] = p2[h];
        }
}

// ------ sparse GAT attention (per hop): aggregate X -> packed (Yhi, Ylo) ------
__global__ void k_attn_agg(int hop) {
    __shared__ float sw[8][HEADSq][KMAX];
    int wl = threadIdx.x >> 5;
    int warp = blockIdx.x * 8 + wl;
    int lane = threadIdx.x & 31;
    if (warp >= ROWS) return;
    int b = warp / Nn;
    int cnt = g_nbr_cnt[warp];
    const int* idx = g_nbr_idx + (size_t)warp * KMAX;
    int d = lane * 4;
    const float* X = g_X4 + (size_t)hop * ROWS * Dd;
    float4 acc[HEADSq];
#pragma unroll
    for (int h = 0; h < HEADSq; h++) acc[h] = make_float4(0.f, 0.f, 0.f, 0.f);

    if (cnt == 0) {
        float4 a = make_float4(0.f, 0.f, 0.f, 0.f);
        for (int m = 0; m < Nn; m++) {
            float4 v = *(const float4*)(X + ((size_t)b * Nn + m) * Dd + d);
            a.x += v.x; a.y += v.y; a.z += v.z; a.w += v.w;
        }
        float sc = 1.0f / (float)Nn;
        a.x *= sc; a.y *= sc; a.z *= sc; a.w *= sc;
#pragma unroll
        for (int h = 0; h < HEADSq; h++) acc[h] = a;
    } else {
        float f1h[HEADSq];
#pragma unroll
        for (int h = 0; h < HEADSq; h++)
            f1h[h] = g_f1[((size_t)hop * HEADSq + h) * ROWS + warp];
        float mx[HEADSq];
#pragma unroll
        for (int h = 0; h < HEADSq; h++) mx[h] = -3.4e38f;
        for (int j = lane; j < cnt; j += 32) {
            int m = idx[j];
#pragma unroll
            for (int h = 0; h < HEADSq; h++) {
                float v = f1h[h] + g_f2[((size_t)hop * HEADSq + h) * ROWS + b * Nn + m];
                v = (v >= 0.0f) ? v : ALPHAq * v;
                sw[wl][h][j] = v;
                mx[h] = fmaxf(mx[h], v);
            }
        }
#pragma unroll
        for (int o = 16; o; o >>= 1)
#pragma unroll
            for (int h = 0; h < HEADSq; h++)
                mx[h] = fmaxf(mx[h], __shfl_xor_sync(0xffffffffu, mx[h], o));
        __syncwarp();
        float sum[HEADSq] = {0.f, 0.f, 0.f, 0.f};
        for (int j = lane; j < cnt; j += 32) {
#pragma unroll
            for (int h = 0; h < HEADSq; h++) {
                float w = expf(sw[wl][h][j] - mx[h]);
                sw[wl][h][j] = w;
                sum[h] += w;
            }
        }
#pragma unroll
        for (int o = 16; o; o >>= 1)
#pragma unroll
            for (int h = 0; h < HEADSq; h++)
                sum[h] += __shfl_xor_sync(0xffffffffu, sum[h], o);
        float sc[HEADSq];
#pragma unroll
        for (int h = 0; h < HEADSq; h++) sc[h] = 1.0f / sum[h];
        __syncwarp();

        // -------- gather, unrolled x4 for MLP --------
        int j = 0;
        for (; j + 4 <= cnt; j += 4) {
            int m0 = idx[j], m1 = idx[j + 1], m2 = idx[j + 2], m3 = idx[j + 3];
            float4 x0 = *(const float4*)(X + ((size_t)b * Nn + m0) * Dd + d);
            float4 x1 = *(const float4*)(X + ((size_t)b * Nn + m1) * Dd + d);
            float4 x2 = *(const float4*)(X + ((size_t)b * Nn + m2) * Dd + d);
            float4 x3 = *(const float4*)(X + ((size_t)b * Nn + m3) * Dd + d);
#pragma unroll
            for (int h = 0; h < HEADSq; h++) {
                float w0 = sw[wl][h][j]     * sc[h];
                float w1 = sw[wl][h][j + 1] * sc[h];
                float w2 = sw[wl][h][j + 2] * sc[h];
                float w3 = sw[wl][h][j + 3] * sc[h];
                acc[h].x += w0 * x0.x + w1 * x1.x + w2 * x2.x + w3 * x3.x;
                acc[h].y += w0 * x0.y + w1 * x1.y + w2 * x2.y + w3 * x3.y;
                acc[h].z += w0 * x0.z + w1 * x1.z + w2 * x2.z + w3 * x3.z;
                acc[h].w += w0 * x0.w + w1 * x1.w + w2 * x2.w + w3 * x3.w;
            }
        }
        for (; j < cnt; j++) {
            int m = idx[j];
            float4 xv = *(const float4*)(X + ((size_t)b * Nn + m) * Dd + d);
#pragma unroll
            for (int h = 0; h < HEADSq; h++) {
                float w = sw[wl][h][j] * sc[h];
                acc[h].x += w * xv.x; acc[h].y += w * xv.y;
                acc[h].z += w * xv.z; acc[h].w += w * xv.w;
            }
        }
    }
    size_t base = (size_t)warp * K2TOT;
#pragma unroll
    for (int h = 0; h < HEADSq; h++) {
        float hx, lx, hy, ly, hz, lz, hw, lw;
        split_bf16(acc[h].x, hx, lx);
        split_bf16(acc[h].y, hy, ly);
        split_bf16(acc[h].z, hz, lz);
        split_bf16(acc[h].w, hw, lw);
        uint2 whi = make_uint2(pack2(hx, hy), pack2(hz, hw));
        uint2 wlo = make_uint2(pack2(lx, ly), pack2(lz, lw));
        *(uint2*)(g_Yhi + base + h * 64 + lane * 2) = whi;
        *(uint2*)(g_Ylo + base + h * 64 + lane * 2) = wlo;
    }
}

// ------ G[hop] = 0.25 * Y (16384x512) @ W[hop] (512x128), 3x bf16 MMA ------
// (exact R6 configuration: 128-row tiles, 128 CTAs, 256 threads)
__global__ void __launch_bounds__(256) k_gemm_G(int hop) {
    __shared__ unsigned Ah[2][128][9];   // [m][k2] (8 words + pad)
    __shared__ unsigned Al[2][128][9];
    __shared__ unsigned Bh[2][8][132];   // [k2][n]
    __shared__ unsigned Bl[2][8][132];
    int row0 = blockIdx.x * 128;
    const unsigned* AH = g_Yhi + (size_t)row0 * K2TOT;
    const unsigned* AL = g_Ylo + (size_t)row0 * K2TOT;
    const unsigned* BH = g_Whi + (size_t)hop * K2TOT * Dd;
    const unsigned* BL = g_Wlo + (size_t)hop * K2TOT * Dd;
    int tid = threadIdx.x;
    int lane = tid & 31, wid = tid >> 5;
    int wm = wid & 3, wn = wid >> 2;          // warp tile 32m x 64n
    int gid = lane >> 2, tig = lane & 3;

    int am = tid >> 1;                         // 0..127
    int aw0 = (tid & 1) * 4;                   // word 0 or 4
    int bk2 = tid >> 5;                        // 0..7
    int bn0 = lane * 4;

    uint4 pah, pal, pbh, pbl;
    pah = *(const uint4*)(AH + (size_t)am * K2TOT + aw0);
    pal = *(const uint4*)(AL + (size_t)am * K2TOT + aw0);
    pbh = *(const uint4*)(BH + (size_t)bk2 * Dd + bn0);
    pbl = *(const uint4*)(BL + (size_t)bk2 * Dd + bn0);
    Ah[0][am][aw0 + 0] = pah.x; Ah[0][am][aw0 + 1] = pah.y;
    Ah[0][am][aw0 + 2] = pah.z; Ah[0][am][aw0 + 3] = pah.w;
    Al[0][am][aw0 + 0] = pal.x; Al[0][am][aw0 + 1] = pal.y;
    Al[0][am][aw0 + 2] = pal.z; Al[0][am][aw0 + 3] = pal.w;
    *(uint4*)&Bh[0][bk2][bn0] = pbh;
    *(uint4*)&Bl[0][bk2][bn0] = pbl;
    __syncthreads();

    float acc[2][8][4];
#pragma unroll
    for (int mt = 0; mt < 2; mt++)
#pragma unroll
        for (int nt = 0; nt < 8; nt++)
#pragma unroll
            for (int q = 0; q < 4; q++) acc[mt][nt][q] = 0.0f;

    int buf = 0;
    const int NSTEP = K2TOT / 8;               // 32 chunks of k2=8 (k=16)
    for (int kt = 0; kt < NSTEP; kt++) {
        if (kt < NSTEP - 1) {
            int k0 = (kt + 1) * 8;
            pah = *(const uint4*)(AH + (size_t)am * K2TOT + k0 + aw0);
            pal = *(const uint4*)(AL + (size_t)am * K2TOT + k0 + aw0);
            pbh = *(const uint4*)(BH + (size_t)(k0 + bk2) * Dd + bn0);
            pbl = *(const uint4*)(BL + (size_t)(k0 + bk2) * Dd + bn0);
        }
        unsigned ah[2][4], al[2][4];
#pragma unroll
        for (int mt = 0; mt < 2; mt++) {
            int m0 = wm * 32 + mt * 16 + gid;
            ah[mt][0] = Ah[buf][m0][tig];
            ah[mt][1] = Ah[buf][m0 + 8][tig];
            ah[mt][2] = Ah[buf][m0][tig + 4];
            ah[mt][3] = Ah[buf][m0 + 8][tig + 4];
            al[mt][0] = Al[buf][m0][tig];
            al[mt][1] = Al[buf][m0 + 8][tig];
            al[mt][2] = Al[buf][m0][tig + 4];
            al[mt][3] = Al[buf][m0 + 8][tig + 4];
        }
#pragma unroll
        for (int nt = 0; nt < 8; nt++) {
            int n0 = wn * 64 + nt * 8 + gid;
            unsigned bh[2], bl[2];
            bh[0] = Bh[buf][tig][n0];
            bh[1] = Bh[buf][tig + 4][n0];
            bl[0] = Bl[buf][tig][n0];
            bl[1] = Bl[buf][tig + 4][n0];
#pragma unroll
            for (int mt = 0; mt < 2; mt++) {
                mma_bf16(acc[mt][nt], ah[mt], bh);
                mma_bf16(acc[mt][nt], al[mt], bh);
                mma_bf16(acc[mt][nt], ah[mt], bl);
            }
        }
        if (kt < NSTEP - 1) {
            buf ^= 1;
            Ah[buf][am][aw0 + 0] = pah.x; Ah[buf][am][aw0 + 1] = pah.y;
            Ah[buf][am][aw0 + 2] = pah.z; Ah[buf][am][aw0 + 3] = pah.w;
            Al[buf][am][aw0 + 0] = pal.x; Al[buf][am][aw0 + 1] = pal.y;
            Al[buf][am][aw0 + 2] = pal.z; Al[buf][am][aw0 + 3] = pal.w;
            *(uint4*)&Bh[buf][bk2][bn0] = pbh;
            *(uint4*)&Bl[buf][bk2][bn0] = pbl;
            __syncthreads();
        }
    }

    float* G = g_G + ((size_t)hop * ROWS + row0) * Dd;
#pragma unroll
    for (int mt = 0; mt < 2; mt++) {
#pragma unroll
        for (int nt = 0; nt < 8; nt++) {
            int r = wm * 32 + mt * 16 + gid;
            int c = wn * 64 + nt * 8 + 2 * tig;
            float2 o0 = make_float2(acc[mt][nt][0] * 0.25f, acc[mt][nt][1] * 0.25f);
            float2 o1 = make_float2(acc[mt][nt][2] * 0.25f, acc[mt][nt][3] * 0.25f);
            *(float2*)(G + (size_t)r * Dd + c) = o0;
            *(float2*)(G + (size_t)(r + 8) * Dd + c) = o1;
        }
    }
}

// ---------------- hop recurrence (R6 structure) ----------------
__global__ void k_init_u(const float* __restrict__ hidden) {
    int i = blockIdx.x * blockDim.x + threadIdx.x;
    if (i < Bq * Dd) g_u[i] = hidden[i];
}

__global__ void k_logits(int hop) {
    int warp = (blockIdx.x * blockDim.x + threadIdx.x) >> 5;
    int lane = threadIdx.x & 31;
    if (warp >= ROWS) return;
    int b = warp / Nn;
    int d = lane * 4;
    float4 g = *(const float4*)(g_G + ((size_t)hop * ROWS + warp) * Dd + d);
    float4 u = *(const float4*)(g_u + (size_t)b * Dd + d);
    float s = g.x * u.x + g.y * u.y + g.z * u.z + g.w * u.w;
#pragma unroll
    for (int o = 16; o; o >>= 1) s += __shfl_xor_sync(0xffffffffu, s, o);
    if (lane == 0) g_logits[warp] = s;
}

__global__ void k_stats() {
    int b = blockIdx.x;
    int tid = threadIdx.x;
    __shared__ float red[256];
    const float* lg = g_logits + (size_t)b * Nn;
    float lmax = -3.4e38f;
    for (int n = tid; n < Nn; n += 256) lmax = fmaxf(lmax, lg[n]);
    red[tid] = lmax; __syncthreads();
    for (int s = 128; s; s >>= 1) { if (tid < s) red[tid] = fmaxf(red[tid], red[tid + s]); __syncthreads(); }
    float mx = red[0]; __syncthreads();
    float lsum = 0.0f;
    for (int n = tid; n < Nn; n += 256) lsum += expf(lg[n] - mx);
    red[tid] = lsum; __syncthreads();
    for (int s = 128; s; s >>= 1) { if (tid < s) red[tid] += red[tid + s]; __syncthreads(); }
    if (tid == 0) { g_stats[b * 2] = mx; g_stats[b * 2 + 1] = 1.0f / red[0]; }
}

__global__ void k_du(int hop) {
    int b = blockIdx.x, c = blockIdx.y;
    int d = threadIdx.x;
    float mx = g_stats[b * 2], inv = g_stats[b * 2 + 1];
    const float* lg = g_logits + (size_t)b * Nn;
    const float* Gn = g_G + (size_t)(hop + 1) * ROWS * Dd + (size_t)b * Nn * Dd;
    int n0 = c * 32;
    float du = 0.0f;
#pragma unroll 4
    for (int j = 0; j < 32; j++) {
        int n = n0 + j;
        float p = expf(lg[n] - mx);
        du += p * Gn[(size_t)n * Dd + d];
    }
    g_dupart[((size_t)b * 32 + c) * Dd + d] = du * inv;
}

__global__ void k_apply() {
    int b = blockIdx.x, d = threadIdx.x;
    const float* part = g_dupart + (size_t)b * 32 * Dd;
    float s = 0.0f;
#pragma unroll
    for (int c = 0; c < 32; c++) s += part[c * Dd + d];
    g_u[(size_t)b * Dd + d] += s;
}

// ---------------- outputs ----------------
__global__ void k_final(float* __restrict__ out) {
    int i = blockIdx.x * blockDim.x + threadIdx.x;
    if (i < ROWS) {
        float l = g_logits[i];
        out[i] = 1.0f / (1.0f + expf(-l));
        out[ROWS + Bq * Dd + i] = l;
    }
    if (i < Bq * Dd) out[ROWS + i] = g_u[i];
}

// ---------------- launch ----------------
extern "C" void kernel_launch(void* const* d_in, const int* in_sizes, int n_in,
                              void* d_out, int out_size) {
    const int*   story  = (const int*)d_in[0];
    const int*   kb     = (const int*)d_in[1];
    const int*   cv     = (const int*)d_in[2];
    const float* hidden = (const float*)d_in[3];
    const float* dh     = (const float*)d_in[4];
    const float* adj    = (const float*)d_in[5];
    const float* emb    = (const float*)d_in[6];
    const float* W      = (const float*)d_in[7];
    const float* a      = (const float*)d_in[8];
    float* out = (float*)d_out;

    k_build_nbr<<<2048, 256>>>(adj, kb, cv);
    k_init_u<<<8, 256>>>(hidden);
    k_proj<<<16, 128>>>(W, a);
    k_split_W<<<(NHOP * K2TOT * Dd + 255) / 256, 256>>>(W);
    k_embed_f<<<dim3(2048, NHOP), 256>>>(story, kb, cv, dh, emb);

    for (int k = 0; k < NHOP; k++) {
        k_attn_agg<<<2048, 256>>>(k);
        k_gemm_G<<<128, 256>>>(k);
    }

    for (int hop = 0; hop < HOPSq; hop++) {
        k_logits<<<2048, 256>>>(hop);
        k_stats<<<Bq, 256>>>();
        k_du<<<dim3(Bq, 32), 128>>>(hop);
        k_apply<<<Bq, 128>>>();
    }
    k_final<<<(ROWS + 255) / 256, 256>>>(out);
}

// round 10
// speedup vs baseline: 1.5058x; 1.0762x over previous
#include <cuda_runtime.h>
#include <cuda_bf16.h>
#include <math.h>

#define Bq     16
#define Nn     1024
#define Dd     128
#define VOCABq 32000
#define HOPSq  3
#define HEADSq 4
#define KMAX   128
#define ALPHAq 0.2f
#define ROWS   (Bq * Nn)   // 16384
#define KTOT   512
#define K2TOT  256          // packed bf16x2 words per row
#define NHOP   (HOPSq + 1)

// ---------------- device scratch ----------------
__device__ int      g_nbr_idx[ROWS * KMAX];
__device__ int      g_nbr_cnt[ROWS];
__device__ float    g_X4[NHOP * ROWS * Dd];
__device__ float    g_wa1[16 * Dd];
__device__ float    g_wa2[16 * Dd];
__device__ float    g_f1p[NHOP * ROWS * 4];      // head-major float4 per row
__device__ float    g_f2p[NHOP * ROWS * 4];
__device__ unsigned g_Yhi[NHOP * ROWS * K2TOT];  // per-hop bf16x2 hi
__device__ unsigned g_Ylo[NHOP * ROWS * K2TOT];  // per-hop bf16x2 lo
__device__ unsigned g_Whi[NHOP * K2TOT * Dd];
__device__ unsigned g_Wlo[NHOP * K2TOT * Dd];
__device__ float    g_G[NHOP * ROWS * Dd];
__device__ float    g_u[Bq * Dd];
__device__ float    g_logits[ROWS];
__device__ float    g_dupart[Bq * 32 * Dd];

// ---------------- bf16 helpers ----------------
__device__ __forceinline__ void split_bf16(float x, float& hi, float& lo) {
    __nv_bfloat16 h = __float2bfloat16_rn(x);
    hi = __bfloat162float(h);
    lo = x - hi;
}
__device__ __forceinline__ unsigned pack2(float e0, float e1) {
    __nv_bfloat162 p = __floats2bfloat162_rn(e0, e1);
    return *reinterpret_cast<unsigned*>(&p);
}
__device__ __forceinline__ void mma_bf16(float* c, const unsigned* a, const unsigned* b) {
    asm volatile(
        "mma.sync.aligned.m16n8k16.row.col.f32.bf16.bf16.f32 "
        "{%0,%1,%2,%3}, {%4,%5,%6,%7}, {%8,%9}, {%0,%1,%2,%3};"
        : "+f"(c[0]), "+f"(c[1]), "+f"(c[2]), "+f"(c[3])
        : "r"(a[0]), "r"(a[1]), "r"(a[2]), "r"(a[3]), "r"(b[0]), "r"(b[1]));
}

// ---------------- neighbor list (float4 + warp scan) ----------------
__global__ void k_build_nbr(const float* __restrict__ adj,
                            const int* __restrict__ kb_len,
                            const int* __restrict__ conv_len) {
    int warp = (blockIdx.x * blockDim.x + threadIdx.x) >> 5;
    int lane = threadIdx.x & 31;
    if (warp >= ROWS) return;
    int b = warp / Nn, n = warp % Nn;
    int ctx = kb_len[b] + conv_len[b];
    const float* arow = adj + (size_t)warp * Nn;
    int* idx = g_nbr_idx + (size_t)warp * KMAX;
    int cnt = 0;
    bool self_ok = (n >= ctx);
    for (int m0 = 0; m0 < Nn; m0 += 128) {
        int mb = m0 + lane * 4;
        float4 a = *(const float4*)(arow + mb);
        bool s0 = (a.x > 0.0f) || (self_ok && mb == n);
        bool s1 = (a.y > 0.0f) || (self_ok && mb + 1 == n);
        bool s2 = (a.z > 0.0f) || (self_ok && mb + 2 == n);
        bool s3 = (a.w > 0.0f) || (self_ok && mb + 3 == n);
        int loc = (int)s0 + (int)s1 + (int)s2 + (int)s3;
        int sc = loc;
#pragma unroll
        for (int o = 1; o < 32; o <<= 1) {
            int t = __shfl_up_sync(0xffffffffu, sc, o);
            if (lane >= o) sc += t;
        }
        int w = cnt + sc - loc;
        if (s0) { if (w < KMAX) idx[w] = mb;     w++; }
        if (s1) { if (w < KMAX) idx[w] = mb + 1; w++; }
        if (s2) { if (w < KMAX) idx[w] = mb + 2; w++; }
        if (s3) { if (w < KMAX) idx[w] = mb + 3; w++; }
        cnt += __shfl_sync(0xffffffffu, sc, 31);
    }
    if (lane == 0) g_nbr_cnt[warp] = cnt < KMAX ? cnt : KMAX;
}

// ---------------- wa = W @ a ----------------
__global__ void k_proj(const float* __restrict__ W_all, const float* __restrict__ a_all) {
    int hh = blockIdx.x;
    int d = threadIdx.x;
    const float* Wrow = W_all + ((size_t)hh * Dd + d) * Dd;
    const float* a = a_all + (size_t)hh * 2 * Dd;
    float s1 = 0.f, s2 = 0.f;
#pragma unroll 4
    for (int e = 0; e < Dd; e++) {
        float w = Wrow[e];
        s1 += w * a[e];
        s2 += w * a[Dd + e];
    }
    g_wa1[hh * Dd + d] = s1;
    g_wa2[hh * Dd + d] = s2;
}

// ---------------- pre-split W into packed bf16 hi/lo ([k2][n]) ----------------
__global__ void k_split_W(const float* __restrict__ W_all) {
    size_t i = (size_t)blockIdx.x * blockDim.x + threadIdx.x;
    if (i >= (size_t)NHOP * K2TOT * Dd) return;
    size_t hop = i / ((size_t)K2TOT * Dd);
    size_t r = i % ((size_t)K2TOT * Dd);
    size_t k2 = r / Dd, nn = r % Dd;
    const float* Wh = W_all + hop * KTOT * Dd;
    float w0 = Wh[(2 * k2) * Dd + nn];
    float w1 = Wh[(2 * k2 + 1) * Dd + nn];
    float h0, l0, h1, l1;
    split_bf16(w0, h0, l0);
    split_bf16(w1, h1, l1);
    g_Whi[i] = pack2(h0, h1);
    g_Wlo[i] = pack2(l0, l1);
}

// ---------------- embedding + LM add + fused f1/f2 (all hops) ----------------
__global__ void k_embed_f(const int* __restrict__ story,
                          const int* __restrict__ kb_len,
                          const int* __restrict__ conv_len,
                          const float* __restrict__ dh,
                          const float* __restrict__ emb) {
    int hop = blockIdx.y;
    __shared__ float swa1[HEADSq * Dd];
    __shared__ float swa2[HEADSq * Dd];
    for (int t = threadIdx.x; t < HEADSq * Dd; t += blockDim.x) {
        swa1[t] = g_wa1[hop * HEADSq * Dd + t];
        swa2[t] = g_wa2[hop * HEADSq * Dd + t];
    }
    __syncthreads();
    int warp = (blockIdx.x * blockDim.x + threadIdx.x) >> 5;
    int lane = threadIdx.x & 31;
    if (warp >= ROWS) return;
    int b = warp / Nn, n = warp % Nn;
    const int* st = story + (size_t)warp * 4;
    int i0 = st[0], i1 = st[1], i2 = st[2], i3 = st[3];
    const float* E = emb + (size_t)hop * VOCABq * Dd;
    int d = lane * 4;
    float4 v0 = *(const float4*)(E + (size_t)i0 * Dd + d);
    float4 v1 = *(const float4*)(E + (size_t)i1 * Dd + d);
    float4 v2 = *(const float4*)(E + (size_t)i2 * Dd + d);
    float4 v3 = *(const float4*)(E + (size_t)i3 * Dd + d);
    float4 s;
    s.x = v0.x + v1.x + v2.x + v3.x;
    s.y = v0.y + v1.y + v2.y + v3.y;
    s.z = v0.z + v1.z + v2.z + v3.z;
    s.w = v0.w + v1.w + v2.w + v3.w;
    int rel = n - (kb_len[b] - 1);
    if (rel >= 0 && rel < conv_len[b]) {
        float4 g = *(const float4*)(dh + ((size_t)b * Nn + rel) * Dd + d);
        s.x += g.x; s.y += g.y; s.z += g.z; s.w += g.w;
    }
    *(float4*)(g_X4 + ((size_t)hop * ROWS + warp) * Dd + d) = s;

    float p1[HEADSq], p2[HEADSq];
#pragma unroll
    for (int h = 0; h < HEADSq; h++) {
        const float* w1 = swa1 + h * Dd + d;
        const float* w2 = swa2 + h * Dd + d;
        p1[h] = s.x * w1[0] + s.y * w1[1] + s.z * w1[2] + s.w * w1[3];
        p2[h] = s.x * w2[0] + s.y * w2[1] + s.z * w2[2] + s.w * w2[3];
    }
#pragma unroll
    for (int o = 16; o; o >>= 1)
#pragma unroll
        for (int h = 0; h < HEADSq; h++) {
            p1[h] += __shfl_xor_sync(0xffffffffu, p1[h], o);
            p2[h] += __shfl_xor_sync(0xffffffffu, p2[h], o);
        }
    if (lane == 0) {
        size_t ro = ((size_t)hop * ROWS + warp) * 4;
        *(float4*)(g_f1p + ro) = make_float4(p1[0], p1[1], p1[2], p1[3]);
        *(float4*)(g_f2p + ro) = make_float4(p2[0], p2[1], p2[2], p2[3]);
    }
}

// ------ sparse GAT attention (per hop): aggregate X -> packed (Yhi, Ylo) ------
__global__ void k_attn_agg(int hop) {
    __shared__ float sw[8][HEADSq][KMAX];
    int wl = threadIdx.x >> 5;
    int warp = blockIdx.x * 8 + wl;
    int lane = threadIdx.x & 31;
    if (warp >= ROWS) return;
    int b = warp / Nn;
    int cnt = g_nbr_cnt[warp];
    const int* idx = g_nbr_idx + (size_t)warp * KMAX;
    int d = lane * 4;
    const float* X = g_X4 + (size_t)hop * ROWS * Dd;
    const float* F2 = g_f2p + (size_t)hop * ROWS * 4 + (size_t)b * Nn * 4;
    float4 acc[HEADSq];
#pragma unroll
    for (int h = 0; h < HEADSq; h++) acc[h] = make_float4(0.f, 0.f, 0.f, 0.f);

    if (cnt == 0) {
        float4 a = make_float4(0.f, 0.f, 0.f, 0.f);
        for (int m = 0; m < Nn; m++) {
            float4 v = *(const float4*)(X + ((size_t)b * Nn + m) * Dd + d);
            a.x += v.x; a.y += v.y; a.z += v.z; a.w += v.w;
        }
        float sc = 1.0f / (float)Nn;
        a.x *= sc; a.y *= sc; a.z *= sc; a.w *= sc;
#pragma unroll
        for (int h = 0; h < HEADSq; h++) acc[h] = a;
    } else {
        float4 f1v = *(const float4*)(g_f1p + ((size_t)hop * ROWS + warp) * 4);
        float f1h[HEADSq] = {f1v.x, f1v.y, f1v.z, f1v.w};
        float mx[HEADSq];
#pragma unroll
        for (int h = 0; h < HEADSq; h++) mx[h] = -3.4e38f;
        for (int j = lane; j < cnt; j += 32) {
            int m = idx[j];
            float4 f2v = *(const float4*)(F2 + (size_t)m * 4);
            float vv[HEADSq] = {f1h[0] + f2v.x, f1h[1] + f2v.y,
                                f1h[2] + f2v.z, f1h[3] + f2v.w};
#pragma unroll
            for (int h = 0; h < HEADSq; h++) {
                float v = vv[h];
                v = (v >= 0.0f) ? v : ALPHAq * v;
                sw[wl][h][j] = v;
                mx[h] = fmaxf(mx[h], v);
            }
        }
#pragma unroll
        for (int o = 16; o; o >>= 1)
#pragma unroll
            for (int h = 0; h < HEADSq; h++)
                mx[h] = fmaxf(mx[h], __shfl_xor_sync(0xffffffffu, mx[h], o));
        __syncwarp();
        float sum[HEADSq] = {0.f, 0.f, 0.f, 0.f};
        for (int j = lane; j < cnt; j += 32) {
#pragma unroll
            for (int h = 0; h < HEADSq; h++) {
                float w = expf(sw[wl][h][j] - mx[h]);
                sw[wl][h][j] = w;
                sum[h] += w;
            }
        }
#pragma unroll
        for (int o = 16; o; o >>= 1)
#pragma unroll
            for (int h = 0; h < HEADSq; h++)
                sum[h] += __shfl_xor_sync(0xffffffffu, sum[h], o);
        float sc[HEADSq];
#pragma unroll
        for (int h = 0; h < HEADSq; h++) sc[h] = 1.0f / sum[h];
        __syncwarp();

        int j = 0;
        for (; j + 4 <= cnt; j += 4) {
            int m0 = idx[j], m1 = idx[j + 1], m2 = idx[j + 2], m3 = idx[j + 3];
            float4 x0 = *(const float4*)(X + ((size_t)b * Nn + m0) * Dd + d);
            float4 x1 = *(const float4*)(X + ((size_t)b * Nn + m1) * Dd + d);
            float4 x2 = *(const float4*)(X + ((size_t)b * Nn + m2) * Dd + d);
            float4 x3 = *(const float4*)(X + ((size_t)b * Nn + m3) * Dd + d);
#pragma unroll
            for (int h = 0; h < HEADSq; h++) {
                float w0 = sw[wl][h][j]     * sc[h];
                float w1 = sw[wl][h][j + 1] * sc[h];
                float w2 = sw[wl][h][j + 2] * sc[h];
                float w3 = sw[wl][h][j + 3] * sc[h];
                acc[h].x += w0 * x0.x + w1 * x1.x + w2 * x2.x + w3 * x3.x;
                acc[h].y += w0 * x0.y + w1 * x1.y + w2 * x2.y + w3 * x3.y;
                acc[h].z += w0 * x0.z + w1 * x1.z + w2 * x2.z + w3 * x3.z;
                acc[h].w += w0 * x0.w + w1 * x1.w + w2 * x2.w + w3 * x3.w;
            }
        }
        for (; j < cnt; j++) {
            int m = idx[j];
            float4 xv = *(const float4*)(X + ((size_t)b * Nn + m) * Dd + d);
#pragma unroll
            for (int h = 0; h < HEADSq; h++) {
                float w = sw[wl][h][j] * sc[h];
                acc[h].x += w * xv.x; acc[h].y += w * xv.y;
                acc[h].z += w * xv.z; acc[h].w += w * xv.w;
            }
        }
    }
    size_t base = ((size_t)hop * ROWS + warp) * K2TOT;
#pragma unroll
    for (int h = 0; h < HEADSq; h++) {
        float hx, lx, hy, ly, hz, lz, hw, lw;
        split_bf16(acc[h].x, hx, lx);
        split_bf16(acc[h].y, hy, ly);
        split_bf16(acc[h].z, hz, lz);
        split_bf16(acc[h].w, hw, lw);
        uint2 whi = make_uint2(pack2(hx, hy), pack2(hz, hw));
        uint2 wlo = make_uint2(pack2(lx, ly), pack2(lz, lw));
        *(uint2*)(g_Yhi + base + h * 64 + lane * 2) = whi;
        *(uint2*)(g_Ylo + base + h * 64 + lane * 2) = wlo;
    }
}

// ------ G = 0.25 * Y @ W, all hops in one launch (grid 128 x NHOP) ------
__global__ void __launch_bounds__(256, 2) k_gemm_G() {
    __shared__ unsigned Ah[2][128][9];
    __shared__ unsigned Al[2][128][9];
    __shared__ unsigned Bh[2][8][132];
    __shared__ unsigned Bl[2][8][132];
    int hop = blockIdx.y;
    int row0 = blockIdx.x * 128;
    const unsigned* AH = g_Yhi + ((size_t)hop * ROWS + row0) * K2TOT;
    const unsigned* AL = g_Ylo + ((size_t)hop * ROWS + row0) * K2TOT;
    const unsigned* BH = g_Whi + (size_t)hop * K2TOT * Dd;
    const unsigned* BL = g_Wlo + (size_t)hop * K2TOT * Dd;
    int tid = threadIdx.x;
    int lane = tid & 31, wid = tid >> 5;
    int wm = wid & 3, wn = wid >> 2;
    int gid = lane >> 2, tig = lane & 3;

    int am = tid >> 1;
    int aw0 = (tid & 1) * 4;
    int bk2 = tid >> 5;
    int bn0 = lane * 4;

    uint4 pah, pal, pbh, pbl;
    pah = *(const uint4*)(AH + (size_t)am * K2TOT + aw0);
    pal = *(const uint4*)(AL + (size_t)am * K2TOT + aw0);
    pbh = *(const uint4*)(BH + (size_t)bk2 * Dd + bn0);
    pbl = *(const uint4*)(BL + (size_t)bk2 * Dd + bn0);
    Ah[0][am][aw0 + 0] = pah.x; Ah[0][am][aw0 + 1] = pah.y;
    Ah[0][am][aw0 + 2] = pah.z; Ah[0][am][aw0 + 3] = pah.w;
    Al[0][am][aw0 + 0] = pal.x; Al[0][am][aw0 + 1] = pal.y;
    Al[0][am][aw0 + 2] = pal.z; Al[0][am][aw0 + 3] = pal.w;
    *(uint4*)&Bh[0][bk2][bn0] = pbh;
    *(uint4*)&Bl[0][bk2][bn0] = pbl;
    __syncthreads();

    float acc[2][8][4];
#pragma unroll
    for (int mt = 0; mt < 2; mt++)
#pragma unroll
        for (int nt = 0; nt < 8; nt++)
#pragma unroll
            for (int q = 0; q < 4; q++) acc[mt][nt][q] = 0.0f;

    int buf = 0;
    const int NSTEP = K2TOT / 8;
    for (int kt = 0; kt < NSTEP; kt++) {
        if (kt < NSTEP - 1) {
            int k0 = (kt + 1) * 8;
            pah = *(const uint4*)(AH + (size_t)am * K2TOT + k0 + aw0);
            pal = *(const uint4*)(AL + (size_t)am * K2TOT + k0 + aw0);
            pbh = *(const uint4*)(BH + (size_t)(k0 + bk2) * Dd + bn0);
            pbl = *(const uint4*)(BL + (size_t)(k0 + bk2) * Dd + bn0);
        }
        unsigned ah[2][4], al[2][4];
#pragma unroll
        for (int mt = 0; mt < 2; mt++) {
            int m0 = wm * 32 + mt * 16 + gid;
            ah[mt][0] = Ah[buf][m0][tig];
            ah[mt][1] = Ah[buf][m0 + 8][tig];
            ah[mt][2] = Ah[buf][m0][tig + 4];
            ah[mt][3] = Ah[buf][m0 + 8][tig + 4];
            al[mt][0] = Al[buf][m0][tig];
            al[mt][1] = Al[buf][m0 + 8][tig];
            al[mt][2] = Al[buf][m0][tig + 4];
            al[mt][3] = Al[buf][m0 + 8][tig + 4];
        }
#pragma unroll
        for (int nt = 0; nt < 8; nt++) {
            int n0 = wn * 64 + nt * 8 + gid;
            unsigned bh[2], bl[2];
            bh[0] = Bh[buf][tig][n0];
            bh[1] = Bh[buf][tig + 4][n0];
            bl[0] = Bl[buf][tig][n0];
            bl[1] = Bl[buf][tig + 4][n0];
#pragma unroll
            for (int mt = 0; mt < 2; mt++) {
                mma_bf16(acc[mt][nt], ah[mt], bh);
                mma_bf16(acc[mt][nt], al[mt], bh);
                mma_bf16(acc[mt][nt], ah[mt], bl);
            }
        }
        if (kt < NSTEP - 1) {
            buf ^= 1;
            Ah[buf][am][aw0 + 0] = pah.x; Ah[buf][am][aw0 + 1] = pah.y;
            Ah[buf][am][aw0 + 2] = pah.z; Ah[buf][am][aw0 + 3] = pah.w;
            Al[buf][am][aw0 + 0] = pal.x; Al[buf][am][aw0 + 1] = pal.y;
            Al[buf][am][aw0 + 2] = pal.z; Al[buf][am][aw0 + 3] = pal.w;
            *(uint4*)&Bh[buf][bk2][bn0] = pbh;
            *(uint4*)&Bl[buf][bk2][bn0] = pbl;
            __syncthreads();
        }
    }

    float* G = g_G + ((size_t)hop * ROWS + row0) * Dd;
#pragma unroll
    for (int mt = 0; mt < 2; mt++) {
#pragma unroll
        for (int nt = 0; nt < 8; nt++) {
            int r = wm * 32 + mt * 16 + gid;
            int c = wn * 64 + nt * 8 + 2 * tig;
            float2 o0 = make_float2(acc[mt][nt][0] * 0.25f, acc[mt][nt][1] * 0.25f);
            float2 o1 = make_float2(acc[mt][nt][2] * 0.25f, acc[mt][nt][3] * 0.25f);
            *(float2*)(G + (size_t)r * Dd + c) = o0;
            *(float2*)(G + (size_t)(r + 8) * Dd + c) = o1;
        }
    }
}

// ---------------- hop recurrence ----------------
__global__ void k_init_u(const float* __restrict__ hidden) {
    int i = blockIdx.x * blockDim.x + threadIdx.x;
    if (i < Bq * Dd) g_u[i] = hidden[i];
}

__global__ void k_logits(int hop) {
    int warp = (blockIdx.x * blockDim.x + threadIdx.x) >> 5;
    int lane = threadIdx.x & 31;
    if (warp >= ROWS) return;
    int b = warp / Nn;
    int d = lane * 4;
    float4 g = *(const float4*)(g_G + ((size_t)hop * ROWS + warp) * Dd + d);
    float4 u = *(const float4*)(g_u + (size_t)b * Dd + d);
    float s = g.x * u.x + g.y * u.y + g.z * u.z + g.w * u.w;
#pragma unroll
    for (int o = 16; o; o >>= 1) s += __shfl_xor_sync(0xffffffffu, s, o);
    if (lane == 0) g_logits[warp] = s;
}

// du with inline softmax stats (grid Bq x 32, 128 threads)
__global__ void k_du(int hop) {
    int b = blockIdx.x, c = blockIdx.y;
    int tid = threadIdx.x;
    __shared__ float red[128];
    const float* lg = g_logits + (size_t)b * Nn;

    float m = -3.4e38f;
#pragma unroll
    for (int i = 0; i < 8; i++) m = fmaxf(m, lg[tid + i * 128]);
    red[tid] = m; __syncthreads();
    for (int s = 64; s; s >>= 1) { if (tid < s) red[tid] = fmaxf(red[tid], red[tid + s]); __syncthreads(); }
    float mx = red[0]; __syncthreads();
    float sum = 0.0f;
#pragma unroll
    for (int i = 0; i < 8; i++) sum += expf(lg[tid + i * 128] - mx);
    red[tid] = sum; __syncthreads();
    for (int s = 64; s; s >>= 1) { if (tid < s) red[tid] += red[tid + s]; __syncthreads(); }
    float inv = 1.0f / red[0];

    const float* Gn = g_G + (size_t)(hop + 1) * ROWS * Dd + (size_t)b * Nn * Dd;
    int n0 = c * 32;
    float du = 0.0f;
#pragma unroll 4
    for (int j = 0; j < 32; j++) {
        int n = n0 + j;
        float p = expf(lg[n] - mx);
        du += p * Gn[(size_t)n * Dd + tid];
    }
    g_dupart[((size_t)b * 32 + c) * Dd + tid] = du * inv;
}

__global__ void k_apply() {
    int b = blockIdx.x, d = threadIdx.x;
    const float* part = g_dupart + (size_t)b * 32 * Dd;
    float s = 0.0f;
#pragma unroll
    for (int c = 0; c < 32; c++) s += part[c * Dd + d];
    g_u[(size_t)b * Dd + d] += s;
}

// ---------------- outputs ----------------
__global__ void k_final(float* __restrict__ out) {
    int i = blockIdx.x * blockDim.x + threadIdx.x;
    if (i < ROWS) {
        float l = g_logits[i];
        out[i] = 1.0f / (1.0f + expf(-l));
        out[ROWS + Bq * Dd + i] = l;
    }
    if (i < Bq * Dd) out[ROWS + i] = g_u[i];
}

// ---------------- launch ----------------
extern "C" void kernel_launch(void* const* d_in, const int* in_sizes, int n_in,
                              void* d_out, int out_size) {
    const int*   story  = (const int*)d_in[0];
    const int*   kb     = (const int*)d_in[1];
    const int*   cv     = (const int*)d_in[2];
    const float* hidden = (const float*)d_in[3];
    const float* dh     = (const float*)d_in[4];
    const float* adj    = (const float*)d_in[5];
    const float* emb    = (const float*)d_in[6];
    const float* W      = (const float*)d_in[7];
    const float* a      = (const float*)d_in[8];
    float* out = (float*)d_out;

    k_build_nbr<<<2048, 256>>>(adj, kb, cv);
    k_init_u<<<8, 256>>>(hidden);
    k_proj<<<16, 128>>>(W, a);
    k_split_W<<<(NHOP * K2TOT * Dd + 255) / 256, 256>>>(W);
    k_embed_f<<<dim3(2048, NHOP), 256>>>(story, kb, cv, dh, emb);

    for (int k = 0; k < NHOP; k++)
        k_attn_agg<<<2048, 256>>>(k);
    k_gemm_G<<<dim3(128, NHOP), 256>>>();

    for (int hop = 0; hop < HOPSq; hop++) {
        k_logits<<<2048, 256>>>(hop);
        k_du<<<dim3(Bq, 32), 128>>>(hop);
        k_apply<<<Bq, 128>>>();
    }
    k_final<<<(ROWS + 255) / 256, 256>>>(out);
}